// round 16
// baseline (speedup 1.0000x reference)
#include <cuda_runtime.h>
#include <cuda_bf16.h>
#include <cstdint>

// ---------------- problem constants ----------------
#define NS      512
#define KSEG    16
#define SEGD    8192
#define FSTRIDE (KSEG * SEGD)
#define OP_SCALE 1.1952286093343936f   // 1/sqrt(0.7) folded per operand
#define NCLASS  10

// ---------------- config ----------------
#define NSM     152                    // persistent: 1 CTA per SM (all resident)
#define NTHREADS 256                   // 4 GEMM warps + 4 convert warps
#define MT      64                     // class tile
#define CK      64                     // bf16 per chunk (128B rows, SW128)
#define KSPLIT  8
#define KQ      (SEGD / KSPLIT)        // 1024
#define CHPU    (KQ / CK)              // 16 chunks per unit
#define STAGES  4
#define OP_BYTES    (MT * 128)         // 8192
#define STAGE_BYTES (2 * OP_BYTES)     // 16384
#define SMEM_DYN (1024 + STAGES * STAGE_BYTES)   // 66560

#define NROWPAD 640
#define MAXP    32
#define NPL     (KSEG * KSPLIT)        // 128 gram planes

// ---------------- device scratch ----------------
__device__ __align__(16) __nv_bfloat16 g_fb16[(size_t)KSEG * NROWPAD * SEGD];
__device__ float g_gram[(size_t)NPL * MAXP * MT * MT];  // 64 MB partials
__device__ float g_partials[2048];
__device__ int   g_red_count;
__device__ int   g_unit;               // GEMM unit queue head
__device__ int   g_segcnt[KSEG];       // convert completion counters
__device__ int   g_segflag[KSEG];      // per-seg release flags
// schedule (rebuilt by prep every launch; deterministic)
__device__ int   g_pos[NS];            // original sample -> grouped row
__device__ int   g_cnum[NCLASS], g_cT[NCLASS], g_cpbase[NCLASS];
__device__ int   g_pairM[MAXP], g_pairN[MAXP];
__device__ int   g_P;

// ---------------- helpers ----------------
__device__ __forceinline__ uint32_t smem_u32(const void* p) {
    uint32_t a;
    asm("{ .reg .u64 t; cvta.to.shared.u64 t, %1; cvt.u32.u64 %0, t; }" : "=r"(a) : "l"(p));
    return a;
}
#define CP16(dst, src) \
    asm volatile("cp.async.cg.shared.global [%0], [%1], 16;" :: "r"(dst), "l"(src))
#define CP_COMMIT() asm volatile("cp.async.commit_group;" ::: "memory")
template <int N> __device__ __forceinline__ void cp_wait() {
    asm volatile("cp.async.wait_group %0;" :: "n"(N) : "memory");
}
#define SW128(o) ((o) ^ (((o) >> 3) & 0x70))
#define BAR_MMA()  asm volatile("bar.sync 1, 128;" ::: "memory")
#define BAR_CONV() asm volatile("bar.sync 2, 128;" ::: "memory")

__device__ __forceinline__ void ldsm_x4(uint32_t& r0, uint32_t& r1, uint32_t& r2, uint32_t& r3,
                                        uint32_t addr) {
    asm volatile("ldmatrix.sync.aligned.m8n8.x4.shared.b16 {%0,%1,%2,%3}, [%4];"
                 : "=r"(r0), "=r"(r1), "=r"(r2), "=r"(r3) : "r"(addr));
}
__device__ __forceinline__ void mma16816(float* c, const uint32_t* a, uint32_t b0, uint32_t b1) {
    asm volatile(
        "mma.sync.aligned.m16n8k16.row.col.f32.bf16.bf16.f32 "
        "{%0,%1,%2,%3}, {%4,%5,%6,%7}, {%8,%9}, {%0,%1,%2,%3};"
        : "+f"(c[0]), "+f"(c[1]), "+f"(c[2]), "+f"(c[3])
        : "r"(a[0]), "r"(a[1]), "r"(a[2]), "r"(a[3]), "r"(b0), "r"(b1));
}

// ---------------------------------------------------------------------------
// Prep (1 block, 512 threads): label dtype detect; stable grouping rank via
// __match_any_sync + per-warp class histograms; tile-pair schedule.
// ---------------------------------------------------------------------------
__global__ void prep_kernel(const int* __restrict__ lab) {
    __shared__ int wcnt[16][NCLASS];
    __shared__ int cnt[NCLASS], cstart[NCLASS];
    const int t = threadIdx.x;
    const int lane = t & 31, w = t >> 5;

    // int32 vs int64: labels 0..9 -> odd 32-bit words all zero iff int64
    int viol = (lab[2 * t + 1] != 0) ? 1 : 0;
    int is32 = __syncthreads_or(viol);
    const int v = is32 ? lab[t] : lab[2 * t];

    if (t < 16 * NCLASS) ((int*)wcnt)[t] = 0;
    __syncthreads();

    const unsigned m = __match_any_sync(0xffffffffu, v);
    const int riw = __popc(m & ((1u << lane) - 1));
    if (lane == (__ffs(m) - 1)) wcnt[w][v] = __popc(m);
    __syncthreads();

    int rank = riw;
    for (int ww = 0; ww < w; ww++) rank += wcnt[ww][v];

    if (t < NCLASS) {
        int s = 0;
        for (int ww = 0; ww < 16; ww++) s += wcnt[ww][t];
        cnt[t] = s;
    }
    __syncthreads();

    if (t == 0) {
        int start = 0, P = 0;
        for (int c = 0; c < NCLASS; c++) {
            const int n = cnt[c];
            cstart[c] = start;
            g_cnum[c] = n;
            const int T = (n + MT - 1) / MT;
            g_cT[c] = T;
            g_cpbase[c] = P;
            for (int ti = 0; ti < T; ti++)
                for (int tj = ti; tj < T; tj++) {
                    if (P < MAXP) { g_pairM[P] = start + MT * ti; g_pairN[P] = start + MT * tj; }
                    P++;
                }
            start += n;
        }
        g_P = (P > MAXP) ? MAXP : P;
    }
    __syncthreads();
    g_pos[t] = cstart[v] + rank;
}

// ---------------------------------------------------------------------------
// Fused persistent convert + block-diagonal GEMM. 152 CTAs (all co-resident),
// 256 threads:
//   warps 0-3 (tid 0-127)  : R10's cp.async/ldmatrix GEMM, atomic unit queue,
//                            units seg-major, gated by per-seg flags.
//   warps 4-7 (tid 128-255): f32 -> bf16 grouped convert (R4 traffic pattern),
//                            seg-by-seg; 152-CTA counter releases flag[s].
// Deterministic: every unit writes a disjoint gram plane; queue order is
// irrelevant to output. Deadlock-free: convert warps never wait on GEMM.
// ---------------------------------------------------------------------------
__global__ void __launch_bounds__(NTHREADS)
fused_kernel(const float* __restrict__ F) {
    extern __shared__ __align__(1024) char smem_raw[];
    __shared__ int s_unit;
    const int tid = threadIdx.x;
    const int cta = blockIdx.x;

    if (tid >= 128) {
        // ---------------- producer: convert warps ----------------
        const int tc = tid - 128;                   // 0..127
        const uint32_t UPS = (NS * SEGD) / 8;       // 524288 8-elem groups / seg
        const uint32_t lo = (uint32_t)(((uint64_t)cta * UPS) / NSM);
        const uint32_t hi = (uint32_t)(((uint64_t)(cta + 1) * UPS) / NSM);
        for (int s = 0; s < KSEG; s++) {
#pragma unroll 4
            for (uint32_t i = lo + tc; i < hi; i += 128) {
                const uint32_t e = i * 8;
                const uint32_t n = e >> 13, d = e & 8191;     // SEGD = 8192
                const float4* src = (const float4*)(F + (size_t)n * FSTRIDE
                                                      + (size_t)s * SEGD + d);
                float4 a = src[0], b = src[1];
                a.x *= OP_SCALE; a.y *= OP_SCALE; a.z *= OP_SCALE; a.w *= OP_SCALE;
                b.x *= OP_SCALE; b.y *= OP_SCALE; b.z *= OP_SCALE; b.w *= OP_SCALE;
                __nv_bfloat162 h0 = __floats2bfloat162_rn(a.x, a.y);
                __nv_bfloat162 h1 = __floats2bfloat162_rn(a.z, a.w);
                __nv_bfloat162 h2 = __floats2bfloat162_rn(b.x, b.y);
                __nv_bfloat162 h3 = __floats2bfloat162_rn(b.z, b.w);
                uint4 w;
                w.x = *(uint32_t*)&h0; w.y = *(uint32_t*)&h1;
                w.z = *(uint32_t*)&h2; w.w = *(uint32_t*)&h3;
                *(uint4*)(g_fb16 + ((size_t)s * NROWPAD + g_pos[n]) * SEGD + d) = w;
            }
            BAR_CONV();
            if (tc == 0) {
                __threadfence();
                if (atomicAdd(&g_segcnt[s], 1) == NSM - 1) {
                    __threadfence();
                    atomicExch(&g_segflag[s], 1);   // release segment s
                }
            }
        }
        return;
    }

    // ---------------- consumer: 4 GEMM warps ----------------
    const uint32_t sbase = (smem_u32(smem_raw) + 1023) & ~1023u;
    const int lane = tid & 31;
    const int wid  = tid >> 5;
    const int wm   = wid & 1;
    const int wn   = wid >> 1;
    const int lrow = lane & 15;
    const int khf  = (lane >> 4) & 1;
    const int gid  = lane >> 2, tig = lane & 3;

    const int P      = g_P;
    const int UPSEG  = P * KSPLIT;
    const int NUNITS = KSEG * UPSEG;
    int lastSeg = -1;

    for (;;) {
        if (tid == 0) s_unit = atomicAdd(&g_unit, 1);
        BAR_MMA();
        const int u = s_unit;
        if (u >= NUNITS) break;

        const int seg  = u / UPSEG;
        const int r    = u - seg * UPSEG;
        const int pidx = r % P;
        const int kq   = r / P;

        if (seg != lastSeg) {                        // acquire producer flag
            if (tid == 0) {
                while (atomicAdd(&g_segflag[seg], 0) == 0) __nanosleep(200);
            }
            BAR_MMA();
            lastSeg = seg;
        }

        const int Moff = g_pairM[pidx];
        const int Noff = g_pairN[pidx];
        const bool diag = (Moff == Noff);

        const __nv_bfloat16* gA = g_fb16 + ((size_t)seg * NROWPAD + Moff) * SEGD
                                         + (size_t)kq * KQ;
        const __nv_bfloat16* gB = g_fb16 + ((size_t)seg * NROWPAD + Noff) * SEGD
                                         + (size_t)kq * KQ;

        float acc[2][4][4];
#pragma unroll
        for (int i = 0; i < 2; i++)
#pragma unroll
            for (int j = 0; j < 4; j++)
#pragma unroll
                for (int q = 0; q < 4; q++) acc[i][j][q] = 0.0f;

        auto load_chunk = [&](int c) {
            const uint32_t st = sbase + (c & (STAGES - 1)) * STAGE_BYTES;
            const int kb = c * CK;
#pragma unroll
            for (int i = 0; i < 4; i++) {            // A: 512 x 16B over 128 thr
                const int q = i * 128 + tid;
                const int row = q >> 3, g = q & 7;
                CP16(st + SW128(row * 128 + g * 16),
                     gA + (size_t)row * SEGD + kb + g * 8);
            }
            if (!diag) {
#pragma unroll
                for (int i = 0; i < 4; i++) {
                    const int q = i * 128 + tid;
                    const int row = q >> 3, g = q & 7;
                    CP16(st + OP_BYTES + SW128(row * 128 + g * 16),
                         gB + (size_t)row * SEGD + kb + g * 8);
                }
            }
            CP_COMMIT();
        };

        auto compute = [&](int cs) {
            const uint32_t sa = sbase + cs * STAGE_BYTES;
            const uint32_t sb = diag ? sa : (sa + OP_BYTES);
#pragma unroll
            for (int ks = 0; ks < 4; ks++) {
                const int kb = ks * 32 + khf * 16;
                uint32_t a[2][4], bf[2][4];
#pragma unroll
                for (int im = 0; im < 2; im++) {
                    const int row = wm * 32 + im * 16 + lrow;
                    ldsm_x4(a[im][0], a[im][1], a[im][2], a[im][3],
                            sa + SW128(row * 128 + kb));
                }
#pragma unroll
                for (int j2 = 0; j2 < 2; j2++) {
                    const int row = wn * 32 + j2 * 16 + lrow;
                    ldsm_x4(bf[j2][0], bf[j2][1], bf[j2][2], bf[j2][3],
                            sb + SW128(row * 128 + kb));
                }
#pragma unroll
                for (int im = 0; im < 2; im++)
#pragma unroll
                    for (int jn = 0; jn < 4; jn++)
                        mma16816(acc[im][jn], a[im],
                                 bf[jn >> 1][jn & 1], bf[jn >> 1][2 + (jn & 1)]);
            }
        };

        load_chunk(0); load_chunk(1); load_chunk(2);
        for (int c = 0; c < CHPU; c++) {
            cp_wait<2>();
            BAR_MMA();
            compute(c & (STAGES - 1));
            if (c + 3 < CHPU) load_chunk(c + 3);
            else CP_COMMIT();             // empty group keeps wait<2> semantics
        }

        float* Cb = g_gram + ((size_t)(seg * KSPLIT + kq) * MAXP + pidx) * (MT * MT);
#pragma unroll
        for (int im = 0; im < 2; im++) {
#pragma unroll
            for (int nb = 0; nb < 4; nb++) {
                const int r0 = wm * 32 + im * 16 + gid;
                const int c0 = wn * 32 + nb * 8 + tig * 2;
                *(float2*)&Cb[r0 * MT + c0] =
                    make_float2(acc[im][nb][0], acc[im][nb][1]);
                *(float2*)&Cb[(r0 + 8) * MT + c0] =
                    make_float2(acc[im][nb][2], acc[im][nb][3]);
            }
        }
        // stage reuse safe: last cp_wait<2>/BAR pair ordered all warps past
        // the stages the next unit's prologue overwrites.
    }
}

// ---------------------------------------------------------------------------
// Loss over within-class pairs only (i < j, weight 2). Sums 8 K-partials,
// top-4-of-16 exp ratio; deterministic tree reduce; last block writes mean
// and resets queue/flags/counters for graph replay.
// NOTE: gram values already carry 1/T (OP_SCALE fold in convert) -> use the
// raw difference in expf. NO extra 1/0.7 factor here (R15's one-line bug).
// ---------------------------------------------------------------------------
__global__ __launch_bounds__(256) void reduce_kernel(float* __restrict__ out) {
    const int t     = threadIdx.x;
    const int c     = blockIdx.x >> 6;
    const int local = ((blockIdx.x & 63) << 8) + t;
    const int i = local >> 7;
    const int j = local & 127;

    float loss = 0.0f;
    const int nc = g_cnum[c];
    if (i < j && j < nc) {
        const int T  = g_cT[c];
        const int ti = i >> 6, tj = j >> 6;
        const int pidx = g_cpbase[c] + ti * T - (ti * (ti - 1)) / 2 + (tj - ti);
        const int cell = (i & 63) * MT + (j & 63);

        float v[KSEG];
        float m = -1e30f;
#pragma unroll
        for (int k = 0; k < KSEG; k++) {
            float s = 0.0f;
#pragma unroll
            for (int kq = 0; kq < KSPLIT; kq++)
                s += g_gram[((size_t)(k * KSPLIT + kq) * MAXP + pidx) * (MT * MT) + cell];
            v[k] = s;
            m = fmaxf(m, s);
        }
        float tot = 0.0f, t0 = 0.0f, t1 = 0.0f, t2 = 0.0f, t3 = 0.0f;
#pragma unroll
        for (int k = 0; k < KSEG; k++) {
            const float e = __expf(v[k] - m);       // FIXED: no double scale
            tot += e;
            if (e > t0)      { t3 = t2; t2 = t1; t1 = t0; t0 = e; }
            else if (e > t1) { t3 = t2; t2 = t1; t1 = e; }
            else if (e > t2) { t3 = t2; t2 = e; }
            else if (e > t3) { t3 = e; }
        }
        loss = -2.0f * __logf((t0 + t1 + t2 + t3) / tot);   // both (a,b),(b,a)
    }

    __shared__ float red[256];
    red[t] = loss;
    __syncthreads();
#pragma unroll
    for (int s = 128; s > 0; s >>= 1) {
        if (t < s) red[t] += red[t + s];
        __syncthreads();
    }

    __shared__ int isLast;
    if (t == 0) {
        g_partials[blockIdx.x] = red[0];
        __threadfence();
        int cn = atomicAdd(&g_red_count, 1);
        isLast = (cn == gridDim.x - 1);
    }
    __syncthreads();

    if (isLast) {
        float s = __ldcg(&g_partials[t]) + __ldcg(&g_partials[t + 256]);
        if (t + 512 < 640) s += __ldcg(&g_partials[t + 512]);
        red[t] = s;
        __syncthreads();
#pragma unroll
        for (int sh = 128; sh > 0; sh >>= 1) {
            if (t < sh) red[t] += red[t + sh];
            __syncthreads();
        }
        if (t == 0) {
            out[0] = red[0] / (float)(NS * NS);
            g_red_count = 0;                        // resets for graph replay
            g_unit = 0;
#pragma unroll
            for (int k = 0; k < KSEG; k++) { g_segcnt[k] = 0; g_segflag[k] = 0; }
        }
    }
}

// ---------------------------------------------------------------------------
extern "C" void kernel_launch(void* const* d_in, const int* in_sizes, int n_in,
                              void* d_out, int out_size) {
    const float* features = (const float*)d_in[0];
    const int*   labels   = (const int*)d_in[1];
    (void)in_sizes; (void)n_in; (void)out_size;

    cudaFuncSetAttribute(fused_kernel, cudaFuncAttributeMaxDynamicSharedMemorySize, SMEM_DYN);

    prep_kernel<<<1, NS>>>(labels);
    fused_kernel<<<NSM, NTHREADS, SMEM_DYN>>>(features);
    reduce_kernel<<<NCLASS * 64, 256>>>((float*)d_out);
}

// round 17
// speedup vs baseline: 2.7856x; 2.7856x over previous
#include <cuda_runtime.h>
#include <cuda_bf16.h>
#include <cstdint>

// ---------------- problem constants ----------------
#define NS      512
#define KSEG    16
#define SEGD    8192
#define FSTRIDE (KSEG * SEGD)
#define OP_SCALE 1.1952286093343936f   // 1/sqrt(0.7) folded per operand
#define NCLASS  10

// ---------------- GEMM config ----------------
#define MT      64                     // class tile
#define CK      64                     // bf16 per chunk (128B rows, SW128)
#define KSPLIT  4
#define KQ      (SEGD / KSPLIT)        // 2048
#define CHPU    (KQ / CK)              // 32 chunks per unit
#define STAGES  3
#define OP_BYTES    (MT * 128)         // 8192 per operand per stage
#define STAGE_BYTES (2 * OP_BYTES)     // 16384
// static smem: 3 * 16384 = 49152 = 48 KB -> 4 CTAs/SM

#define NROWPAD 640
#define MAXP    32
#define NPL     (KSEG * KSPLIT)        // 64 gram planes

// ---------------- device scratch ----------------
__device__ __align__(16) __nv_bfloat16 g_fb16[(size_t)NS * FSTRIDE]; // identity layout
__device__ float g_gram[(size_t)NPL * MAXP * MT * MT];  // 33.5 MB partials
__device__ float g_partials[2048];
__device__ int   g_red_count;
// schedule (rebuilt by prep every launch; deterministic)
__device__ int   g_rowsrc[NROWPAD];    // grouped row -> original sample (pad->0)
__device__ int   g_cnum[NCLASS], g_cT[NCLASS], g_cpbase[NCLASS];
__device__ int   g_pairM[MAXP], g_pairN[MAXP];
__device__ int   g_P;

// ---------------- helpers ----------------
__device__ __forceinline__ uint32_t smem_u32(const void* p) {
    uint32_t a;
    asm("{ .reg .u64 t; cvta.to.shared.u64 t, %1; cvt.u32.u64 %0, t; }" : "=r"(a) : "l"(p));
    return a;
}
#define CP16(dst, src) \
    asm volatile("cp.async.cg.shared.global [%0], [%1], 16;" :: "r"(dst), "l"(src))
#define CP_COMMIT() asm volatile("cp.async.commit_group;" ::: "memory")
template <int N> __device__ __forceinline__ void cp_wait() {
    asm volatile("cp.async.wait_group %0;" :: "n"(N) : "memory");
}
#define SW128(o) ((o) ^ (((o) >> 3) & 0x70))

__device__ __forceinline__ void ldsm_x4(uint32_t& r0, uint32_t& r1, uint32_t& r2, uint32_t& r3,
                                        uint32_t addr) {
    asm volatile("ldmatrix.sync.aligned.m8n8.x4.shared.b16 {%0,%1,%2,%3}, [%4];"
                 : "=r"(r0), "=r"(r1), "=r"(r2), "=r"(r3) : "r"(addr));
}
__device__ __forceinline__ void mma16816(float* c, const uint32_t* a, uint32_t b0, uint32_t b1) {
    asm volatile(
        "mma.sync.aligned.m16n8k16.row.col.f32.bf16.bf16.f32 "
        "{%0,%1,%2,%3}, {%4,%5,%6,%7}, {%8,%9}, {%0,%1,%2,%3};"
        : "+f"(c[0]), "+f"(c[1]), "+f"(c[2]), "+f"(c[3])
        : "r"(a[0]), "r"(a[1]), "r"(a[2]), "r"(a[3]), "r"(b0), "r"(b1));
}

// ---------------------------------------------------------------------------
// 256-thread prep (runs as block 0 of the convert kernel; 2 samples/thread).
// 16 virtual warps = (round r in {0,1}) x (8 warps): stable rank preserved.
// ---------------------------------------------------------------------------
__device__ void prep256(const int* __restrict__ lab) {
    __shared__ int wcnt[16][NCLASS];   // virtual warp = r*8 + w
    __shared__ int cnt[NCLASS], cstart[NCLASS];
    const int t = threadIdx.x;         // 0..255
    const int lane = t & 31, w = t >> 5;

    // int32 vs int64: labels 0..9 -> odd 32-bit words all zero iff int64
    int viol = (lab[2 * t + 1] != 0) ? 1 : 0;
    int is32 = __syncthreads_or(viol);
    const int v0 = is32 ? lab[t]       : lab[2 * t];
    const int v1 = is32 ? lab[t + 256] : lab[2 * (t + 256)];

    if (t < 16 * NCLASS) ((int*)wcnt)[t] = 0;
    // zero rowsrc (640 entries)
    g_rowsrc[t] = 0; g_rowsrc[t + 256] = 0;
    if (t < NROWPAD - 512) g_rowsrc[t + 512] = 0;
    __syncthreads();

    const unsigned m0 = __match_any_sync(0xffffffffu, v0);
    const int riw0 = __popc(m0 & ((1u << lane) - 1));
    if (lane == (__ffs(m0) - 1)) wcnt[w][v0] = __popc(m0);
    const unsigned m1 = __match_any_sync(0xffffffffu, v1);
    const int riw1 = __popc(m1 & ((1u << lane) - 1));
    if (lane == (__ffs(m1) - 1)) wcnt[8 + w][v1] = __popc(m1);
    __syncthreads();

    int rank0 = riw0, rank1 = riw1;
    for (int vw = 0; vw < w; vw++)      rank0 += wcnt[vw][v0];
    for (int vw = 0; vw < 8 + w; vw++)  rank1 += wcnt[vw][v1];

    if (t < NCLASS) {
        int s = 0;
        for (int vw = 0; vw < 16; vw++) s += wcnt[vw][t];
        cnt[t] = s;
    }
    __syncthreads();

    if (t == 0) {
        int start = 0, P = 0;
        for (int c = 0; c < NCLASS; c++) {
            const int n = cnt[c];
            cstart[c] = start;
            g_cnum[c] = n;
            const int T = (n + MT - 1) / MT;
            g_cT[c] = T;
            g_cpbase[c] = P;
            for (int ti = 0; ti < T; ti++)
                for (int tj = ti; tj < T; tj++) {
                    if (P < MAXP) { g_pairM[P] = start + MT * ti; g_pairN[P] = start + MT * tj; }
                    P++;
                }
            start += n;
        }
        g_P = (P > MAXP) ? MAXP : P;
    }
    __syncthreads();
    g_rowsrc[cstart[v0] + rank0] = t;
    g_rowsrc[cstart[v1] + rank1] = t + 256;
}

// ---------------------------------------------------------------------------
// Convert (blocks 1..) : pure streaming f32 -> bf16, identity layout, scale
// folded. Block 0 does prep concurrently (independent work).
// ---------------------------------------------------------------------------
__global__ __launch_bounds__(256)
void conv_prep_kernel(const float* __restrict__ F, const int* __restrict__ lab) {
    if (blockIdx.x == 0) { prep256(lab); return; }

    const size_t t = (size_t)(blockIdx.x - 1) * 256 + threadIdx.x;
    const size_t e = t * 8;
    const float4* src = (const float4*)(F + e);
    float4 a = src[0], b = src[1];
    a.x *= OP_SCALE; a.y *= OP_SCALE; a.z *= OP_SCALE; a.w *= OP_SCALE;
    b.x *= OP_SCALE; b.y *= OP_SCALE; b.z *= OP_SCALE; b.w *= OP_SCALE;

    __nv_bfloat162 h0 = __floats2bfloat162_rn(a.x, a.y);
    __nv_bfloat162 h1 = __floats2bfloat162_rn(a.z, a.w);
    __nv_bfloat162 h2 = __floats2bfloat162_rn(b.x, b.y);
    __nv_bfloat162 h3 = __floats2bfloat162_rn(b.z, b.w);
    uint4 w;
    w.x = *(uint32_t*)&h0; w.y = *(uint32_t*)&h1;
    w.z = *(uint32_t*)&h2; w.w = *(uint32_t*)&h3;
    *(uint4*)(g_fb16 + e) = w;
}

// ---------------------------------------------------------------------------
// Block-diagonal bf16 Gram GEMM (R10's proven pipeline, 3-stage, 4 CTAs/SM).
// Rows gathered through g_rowsrc in the cp.async source addresses.
// Grid (MAXP, KSEG, KSPLIT); pidx >= g_P exits. 128 threads, 2x2 warp grid
// of 32x32 tiles over a 64x64 class tile. Diagonal pairs skip B (B==A).
// ---------------------------------------------------------------------------
__global__ void __launch_bounds__(128)
gemm_kernel() {
    const int pidx = blockIdx.x;
    if (pidx >= g_P) return;
    const int seg = blockIdx.y;
    const int kq  = blockIdx.z;

    __shared__ __align__(1024) char smem[STAGES * STAGE_BYTES];  // 48 KB
    const uint32_t sbase = smem_u32(smem);

    const int tid  = threadIdx.x;
    const int lane = tid & 31;
    const int wid  = tid >> 5;
    const int wm   = wid & 1;
    const int wn   = wid >> 1;
    const int lrow = lane & 15;
    const int khf  = (lane >> 4) & 1;
    const int gid  = lane >> 2, tig = lane & 3;

    const int Moff = g_pairM[pidx];
    const int Noff = g_pairN[pidx];
    const bool diag = (Moff == Noff);

    // per-thread cp.async sources (gathered rows) and swizzled dests
    const size_t kbase = (size_t)seg * SEGD + (size_t)kq * KQ;
    const __nv_bfloat16* aptr[4];
    const __nv_bfloat16* bptr[4];
    uint32_t dsto[4];
#pragma unroll
    for (int i = 0; i < 4; i++) {
        const int q = i * 128 + tid;
        const int row = q >> 3, u = q & 7;      // 64 rows x 8 16B-units
        aptr[i] = g_fb16 + (size_t)g_rowsrc[Moff + row] * FSTRIDE + kbase + u * 8;
        bptr[i] = g_fb16 + (size_t)g_rowsrc[Noff + row] * FSTRIDE + kbase + u * 8;
        dsto[i] = SW128((uint32_t)(row * 128 + u * 16));
    }

    auto load_chunk = [&](int c) {
        const uint32_t st = sbase + (c % STAGES) * STAGE_BYTES;
        const int koff = c * CK;
#pragma unroll
        for (int i = 0; i < 4; i++)
            CP16(st + dsto[i], aptr[i] + koff);
        if (!diag) {
#pragma unroll
            for (int i = 0; i < 4; i++)
                CP16(st + OP_BYTES + dsto[i], bptr[i] + koff);
        }
        CP_COMMIT();
    };

    float acc[2][4][4];
#pragma unroll
    for (int i = 0; i < 2; i++)
#pragma unroll
        for (int j = 0; j < 4; j++)
#pragma unroll
            for (int q = 0; q < 4; q++) acc[i][j][q] = 0.0f;

    auto compute = [&](int cs) {
        const uint32_t sa = sbase + cs * STAGE_BYTES;
        const uint32_t sb = diag ? sa : (sa + OP_BYTES);
#pragma unroll
        for (int ks = 0; ks < 4; ks++) {
            const int kb = ks * 32 + khf * 16;
            uint32_t a[2][4], bf[2][4];
#pragma unroll
            for (int im = 0; im < 2; im++) {
                const int row = wm * 32 + im * 16 + lrow;
                ldsm_x4(a[im][0], a[im][1], a[im][2], a[im][3],
                        sa + SW128(row * 128 + kb));
            }
#pragma unroll
            for (int j2 = 0; j2 < 2; j2++) {
                const int row = wn * 32 + j2 * 16 + lrow;
                ldsm_x4(bf[j2][0], bf[j2][1], bf[j2][2], bf[j2][3],
                        sb + SW128(row * 128 + kb));
            }
#pragma unroll
            for (int im = 0; im < 2; im++)
#pragma unroll
                for (int jn = 0; jn < 4; jn++)
                    mma16816(acc[im][jn], a[im],
                             bf[jn >> 1][jn & 1], bf[jn >> 1][2 + (jn & 1)]);
        }
    };

    load_chunk(0);
    load_chunk(1);
    for (int c = 0; c < CHPU; c++) {
        cp_wait<1>();
        __syncthreads();
        compute(c % STAGES);
        if (c + 2 < CHPU) load_chunk(c + 2);
        else CP_COMMIT();                 // empty group keeps wait<1> semantics
    }

    float* Cb = g_gram + ((size_t)(seg * KSPLIT + kq) * MAXP + pidx) * (MT * MT);
#pragma unroll
    for (int im = 0; im < 2; im++) {
#pragma unroll
        for (int nb = 0; nb < 4; nb++) {
            const int r0 = wm * 32 + im * 16 + gid;
            const int c0 = wn * 32 + nb * 8 + tig * 2;
            *(float2*)&Cb[r0 * MT + c0] =
                make_float2(acc[im][nb][0], acc[im][nb][1]);
            *(float2*)&Cb[(r0 + 8) * MT + c0] =
                make_float2(acc[im][nb][2], acc[im][nb][3]);
        }
    }
}

// ---------------------------------------------------------------------------
// Loss over within-class pairs only (i < j, weight 2). Sums 4 K-partials,
// top-4-of-16 exp ratio; deterministic tree reduce; last block writes mean.
// Gram already carries 1/T (OP_SCALE fold) -> raw differences in expf.
// ---------------------------------------------------------------------------
__global__ __launch_bounds__(256) void reduce_kernel(float* __restrict__ out) {
    const int t     = threadIdx.x;
    const int c     = blockIdx.x >> 6;
    const int local = ((blockIdx.x & 63) << 8) + t;
    const int i = local >> 7;
    const int j = local & 127;

    float loss = 0.0f;
    const int nc = g_cnum[c];
    if (i < j && j < nc) {
        const int T  = g_cT[c];
        const int ti = i >> 6, tj = j >> 6;
        const int pidx = g_cpbase[c] + ti * T - (ti * (ti - 1)) / 2 + (tj - ti);
        const int cell = (i & 63) * MT + (j & 63);

        float v[KSEG];
        float m = -1e30f;
#pragma unroll
        for (int k = 0; k < KSEG; k++) {
            float s = 0.0f;
#pragma unroll
            for (int kq = 0; kq < KSPLIT; kq++)
                s += g_gram[((size_t)(k * KSPLIT + kq) * MAXP + pidx) * (MT * MT) + cell];
            v[k] = s;
            m = fmaxf(m, s);
        }
        float tot = 0.0f, t0 = 0.0f, t1 = 0.0f, t2 = 0.0f, t3 = 0.0f;
#pragma unroll
        for (int k = 0; k < KSEG; k++) {
            const float e = __expf(v[k] - m);
            tot += e;
            if (e > t0)      { t3 = t2; t2 = t1; t1 = t0; t0 = e; }
            else if (e > t1) { t3 = t2; t2 = t1; t1 = e; }
            else if (e > t2) { t3 = t2; t2 = e; }
            else if (e > t3) { t3 = e; }
        }
        loss = -2.0f * __logf((t0 + t1 + t2 + t3) / tot);   // both (a,b),(b,a)
    }

    __shared__ float red[256];
    red[t] = loss;
    __syncthreads();
#pragma unroll
    for (int s = 128; s > 0; s >>= 1) {
        if (t < s) red[t] += red[t + s];
        __syncthreads();
    }

    __shared__ int isLast;
    if (t == 0) {
        g_partials[blockIdx.x] = red[0];
        __threadfence();
        int cn = atomicAdd(&g_red_count, 1);
        isLast = (cn == gridDim.x - 1);
    }
    __syncthreads();

    if (isLast) {
        float s = __ldcg(&g_partials[t]) + __ldcg(&g_partials[t + 256]);
        if (t + 512 < 640) s += __ldcg(&g_partials[t + 512]);
        red[t] = s;
        __syncthreads();
#pragma unroll
        for (int sh = 128; sh > 0; sh >>= 1) {
            if (t < sh) red[t] += red[t + sh];
            __syncthreads();
        }
        if (t == 0) {
            out[0] = red[0] / (float)(NS * NS);
            g_red_count = 0;           // reset for graph replay
        }
    }
}

// ---------------------------------------------------------------------------
extern "C" void kernel_launch(void* const* d_in, const int* in_sizes, int n_in,
                              void* d_out, int out_size) {
    const float* features = (const float*)d_in[0];
    const int*   labels   = (const int*)d_in[1];
    (void)in_sizes; (void)n_in; (void)out_size;

    // block 0 = prep; blocks 1..32768 = streaming convert
    conv_prep_kernel<<<(NS * FSTRIDE) / (256 * 8) + 1, 256>>>(features, labels);

    dim3 grid(MAXP, KSEG, KSPLIT);     // inactive pairs exit on g_P
    gemm_kernel<<<grid, 128>>>();

    reduce_kernel<<<NCLASS * 64, 256>>>((float*)d_out);
}